// round 1
// baseline (speedup 1.0000x reference)
#include <cuda_runtime.h>
#include <math.h>

// Problem constants
#define NB   4
#define C    256
#define H    64
#define W    64
#define HW   4096
#define NPIX 16384          // NB*H*W
#define G    8
#define GC   32
#define P    9
#define NOFF 144            // G*P*2
#define NMSK 72             // G*P

// -------- scratch (device globals; no allocation allowed) --------
__device__ float g_xnhwc[NPIX * C];   // x transposed to NHWC
__device__ float g_xproj[NPIX * C];   // input projection (NHWC)
__device__ float g_x1   [NPIX * C];   // LN+GELU branch (NHWC)
__device__ float g_off  [NPIX * NOFF];
__device__ float g_mlog [NPIX * NMSK];
__device__ float g_agg  [NPIX * C];   // sampled+aggregated (NHWC)

// ============================================================
// NCHW -> NHWC transpose (per-n 256 x 4096 matrix transpose)
// ============================================================
extern "C" __global__ void __launch_bounds__(256)
transpose_kernel(const float* __restrict__ x)
{
    __shared__ float tile[32][33];
    const int n   = blockIdx.z;
    const int hw0 = blockIdx.x * 32;
    const int c0  = blockIdx.y * 32;
    const float* src = x + (size_t)n * C * HW;
    float*       dst = g_xnhwc + (size_t)n * HW * C;
    #pragma unroll
    for (int i = 0; i < 4; i++) {
        int cl = threadIdx.y + i * 8;
        tile[cl][threadIdx.x] = src[(size_t)(c0 + cl) * HW + hw0 + threadIdx.x];
    }
    __syncthreads();
    #pragma unroll
    for (int i = 0; i < 4; i++) {
        int hl = threadIdx.y + i * 8;
        dst[(size_t)(hw0 + hl) * C + c0 + threadIdx.x] = tile[threadIdx.x][hl];
    }
}

// ============================================================
// Tiled fp32 GEMM body: C[M x N] = A[M x K] @ B[K x N] + bias
// BM=BN=64, BK=16, 256 threads, 4x4 per thread.
// M is always a multiple of 64; K a multiple of 16; N a multiple of 4.
// ============================================================
__device__ __forceinline__ void gemm_body(
    const float* __restrict__ A, const float* __restrict__ B,
    const float* __restrict__ bias, float* __restrict__ Cm,
    int N, int K)
{
    __shared__ float As[16][64];
    __shared__ float Bs[16][64];
    const int bm  = blockIdx.y * 64;
    const int bn  = blockIdx.x * 64;
    const int tid = threadIdx.x;
    const int tx  = tid & 15, ty = tid >> 4;
    const int ar  = tid >> 2, akv = (tid & 3) * 4;
    const int bkr = tid >> 4, bnv = (tid & 15) * 4;

    float acc[4][4] = {};
    for (int k0 = 0; k0 < K; k0 += 16) {
        // stage A (transposed into k-major smem)
        float4 a = *reinterpret_cast<const float4*>(&A[(size_t)(bm + ar) * K + k0 + akv]);
        As[akv + 0][ar] = a.x; As[akv + 1][ar] = a.y;
        As[akv + 2][ar] = a.z; As[akv + 3][ar] = a.w;
        // stage B
        int col = bn + bnv;
        float4 b;
        if (col + 3 < N) {
            b = *reinterpret_cast<const float4*>(&B[(size_t)(k0 + bkr) * N + col]);
        } else {
            b.x = (col + 0 < N) ? B[(size_t)(k0 + bkr) * N + col + 0] : 0.f;
            b.y = (col + 1 < N) ? B[(size_t)(k0 + bkr) * N + col + 1] : 0.f;
            b.z = (col + 2 < N) ? B[(size_t)(k0 + bkr) * N + col + 2] : 0.f;
            b.w = (col + 3 < N) ? B[(size_t)(k0 + bkr) * N + col + 3] : 0.f;
        }
        *reinterpret_cast<float4*>(&Bs[bkr][bnv]) = b;
        __syncthreads();
        #pragma unroll
        for (int k = 0; k < 16; k++) {
            float4 av = *reinterpret_cast<const float4*>(&As[k][ty * 4]);
            float4 bv = *reinterpret_cast<const float4*>(&Bs[k][tx * 4]);
            float ra[4] = {av.x, av.y, av.z, av.w};
            float rb[4] = {bv.x, bv.y, bv.z, bv.w};
            #pragma unroll
            for (int i = 0; i < 4; i++)
                #pragma unroll
                for (int j = 0; j < 4; j++)
                    acc[i][j] += ra[i] * rb[j];
        }
        __syncthreads();
    }
    const int col0 = bn + tx * 4;
    #pragma unroll
    for (int i = 0; i < 4; i++) {
        int row = bm + ty * 4 + i;
        if (col0 + 3 < N) {
            float4 o = {acc[i][0] + bias[col0 + 0], acc[i][1] + bias[col0 + 1],
                        acc[i][2] + bias[col0 + 2], acc[i][3] + bias[col0 + 3]};
            *reinterpret_cast<float4*>(&Cm[(size_t)row * N + col0]) = o;
        } else {
            #pragma unroll
            for (int j = 0; j < 4; j++)
                if (col0 + j < N)
                    Cm[(size_t)row * N + col0 + j] = acc[i][j] + bias[col0 + j];
        }
    }
}

extern "C" __global__ void __launch_bounds__(256)
gemm_in_kernel(const float* __restrict__ B, const float* __restrict__ bias)
{ gemm_body(g_xnhwc, B, bias, g_xproj, C, C); }

extern "C" __global__ void __launch_bounds__(256)
gemm_off_kernel(const float* __restrict__ B, const float* __restrict__ bias)
{ gemm_body(g_x1, B, bias, g_off, NOFF, C); }

extern "C" __global__ void __launch_bounds__(256)
gemm_mask_kernel(const float* __restrict__ B, const float* __restrict__ bias)
{ gemm_body(g_x1, B, bias, g_mlog, NMSK, C); }

// ============================================================
// Depthwise 3x3 (pad 1) + LayerNorm(C) + exact GELU, fused.
// One block per pixel, one thread per channel. NHWC -> fully coalesced.
// ============================================================
extern "C" __global__ void __launch_bounds__(256)
dwln_kernel(const float* __restrict__ w_dw, const float* __restrict__ b_dw,
            const float* __restrict__ ln_g, const float* __restrict__ ln_b)
{
    const int pix = blockIdx.x;
    const int c   = threadIdx.x;
    const int n = pix >> 12, hw = pix & 4095, h = hw >> 6, w = hw & 63;

    float wk[9];
    #pragma unroll
    for (int i = 0; i < 9; i++) wk[i] = w_dw[c * 9 + i];

    float acc = b_dw[c];
    #pragma unroll
    for (int ky = 0; ky < 3; ky++) {
        int yy = h + ky - 1;
        if (yy < 0 || yy > 63) continue;
        #pragma unroll
        for (int kx = 0; kx < 3; kx++) {
            int xx = w + kx - 1;
            if (xx < 0 || xx > 63) continue;
            acc += g_xnhwc[(((size_t)n * 64 + yy) * 64 + xx) * C + c] * wk[ky * 3 + kx];
        }
    }

    __shared__ float red[8];
    // mean
    float s = acc;
    #pragma unroll
    for (int o = 16; o; o >>= 1) s += __shfl_xor_sync(0xffffffffu, s, o);
    if ((c & 31) == 0) red[c >> 5] = s;
    __syncthreads();
    float tot = 0.f;
    #pragma unroll
    for (int i = 0; i < 8; i++) tot += red[i];
    const float mean = tot * (1.f / 256.f);
    __syncthreads();
    // variance (centered, matches reference numerics)
    float d  = acc - mean;
    float s2 = d * d;
    #pragma unroll
    for (int o = 16; o; o >>= 1) s2 += __shfl_xor_sync(0xffffffffu, s2, o);
    if ((c & 31) == 0) red[c >> 5] = s2;
    __syncthreads();
    float tot2 = 0.f;
    #pragma unroll
    for (int i = 0; i < 8; i++) tot2 += red[i];
    const float var = tot2 * (1.f / 256.f);

    float v = d * rsqrtf(var + 1e-5f) * ln_g[c] + ln_b[c];
    // exact GELU: 0.5*v*(1+erf(v/sqrt(2)))
    float ge = 0.5f * v * (1.f + erff(v * 0.70710678118654752f));
    g_x1[(size_t)pix * C + c] = ge;
}

// ============================================================
// Deformable sampling + per-group softmax mask aggregation.
// One block per pixel; warp = group (32 lanes = 32 contiguous channels).
// Math collapses to padded coords: gx = w + p/3 + off_x, gy = h + p%3 + off_y.
// Tap value nonzero iff padded coord in [1,64] (zero pad ring).
// ============================================================
extern "C" __global__ void __launch_bounds__(256)
sample_kernel()
{
    const int pix = blockIdx.x;
    const int t   = threadIdx.x;
    const int g   = t >> 5, cc = t & 31;
    const int n = pix >> 12, hw = pix & 4095, h = hw >> 6, w = hw & 63;

    const float* ob = g_off  + (size_t)pix * NOFF + g * 18;
    const float* lb = g_mlog + (size_t)pix * NMSK + g * 9;

    // softmax over the 9 points (uniform within warp -> broadcast loads)
    float l[9], m = -1e30f;
    #pragma unroll
    for (int p = 0; p < 9; p++) { l[p] = lb[p]; m = fmaxf(m, l[p]); }
    float se = 0.f;
    #pragma unroll
    for (int p = 0; p < 9; p++) { l[p] = expf(l[p] - m); se += l[p]; }
    const float inv = 1.f / se;

    const float* base = g_xproj + (size_t)n * HW * C + g * GC + cc;
    float acc = 0.f;
    #pragma unroll
    for (int p = 0; p < 9; p++) {
        float gx = (float)(w + (p / 3)) + ob[2 * p + 0];
        float gy = (float)(h + (p % 3)) + ob[2 * p + 1];
        float x0f = floorf(gx), y0f = floorf(gy);
        int   x0 = (int)x0f, y0 = (int)y0f;
        float wx = gx - x0f, wy = gy - y0f;
        float w00 = (1.f - wx) * (1.f - wy);
        float w10 = wx * (1.f - wy);
        float w01 = (1.f - wx) * wy;
        float w11 = wx * wy;
        bool yi0 = (y0     >= 1 && y0     <= 64);
        bool yi1 = (y0 + 1 >= 1 && y0 + 1 <= 64);
        bool xi0 = (x0     >= 1 && x0     <= 64);
        bool xi1 = (x0 + 1 >= 1 && x0 + 1 <= 64);
        float v00 = 0.f, v10 = 0.f, v01 = 0.f, v11 = 0.f;
        if (yi0 && xi0) v00 = base[((size_t)(y0 - 1) * 64 + (x0 - 1)) * C];
        if (yi0 && xi1) v10 = base[((size_t)(y0 - 1) * 64 + (x0    )) * C];
        if (yi1 && xi0) v01 = base[((size_t)(y0    ) * 64 + (x0 - 1)) * C];
        if (yi1 && xi1) v11 = base[((size_t)(y0    ) * 64 + (x0    )) * C];
        acc += (l[p] * inv) * (w00 * v00 + w10 * v10 + w01 * v01 + w11 * v11);
    }
    g_agg[(size_t)pix * C + t] = acc;
}

// ============================================================
// Output projection GEMM + bias + BatchNorm(inference) + SiLU,
// writing NCHW. Per-thread float4 stores along the pixel dim
// (contiguous in NCHW for a fixed output channel).
// ============================================================
extern "C" __global__ void __launch_bounds__(256)
gemm_out_kernel(const float* __restrict__ B, const float* __restrict__ bias,
                const float* __restrict__ bn_g, const float* __restrict__ bn_b,
                const float* __restrict__ bn_mean, const float* __restrict__ bn_var,
                float* __restrict__ out)
{
    __shared__ float As[16][64];
    __shared__ float Bs[16][64];
    const int bm  = blockIdx.y * 64;
    const int bn  = blockIdx.x * 64;
    const int tid = threadIdx.x;
    const int tx  = tid & 15, ty = tid >> 4;
    const int ar  = tid >> 2, akv = (tid & 3) * 4;
    const int bkr = tid >> 4, bnv = (tid & 15) * 4;

    float acc[4][4] = {};
    for (int k0 = 0; k0 < C; k0 += 16) {
        float4 a = *reinterpret_cast<const float4*>(&g_agg[(size_t)(bm + ar) * C + k0 + akv]);
        As[akv + 0][ar] = a.x; As[akv + 1][ar] = a.y;
        As[akv + 2][ar] = a.z; As[akv + 3][ar] = a.w;
        *reinterpret_cast<float4*>(&Bs[bkr][bnv]) =
            *reinterpret_cast<const float4*>(&B[(size_t)(k0 + bkr) * C + bn + bnv]);
        __syncthreads();
        #pragma unroll
        for (int k = 0; k < 16; k++) {
            float4 av = *reinterpret_cast<const float4*>(&As[k][ty * 4]);
            float4 bv = *reinterpret_cast<const float4*>(&Bs[k][tx * 4]);
            float ra[4] = {av.x, av.y, av.z, av.w};
            float rb[4] = {bv.x, bv.y, bv.z, bv.w};
            #pragma unroll
            for (int i = 0; i < 4; i++)
                #pragma unroll
                for (int j = 0; j < 4; j++)
                    acc[i][j] += ra[i] * rb[j];
        }
        __syncthreads();
    }

    const int row0 = bm + ty * 4;           // 4 consecutive pixels
    const int n    = row0 >> 12;
    const int hw0  = row0 & 4095;
    #pragma unroll
    for (int j = 0; j < 4; j++) {
        int col = bn + tx * 4 + j;
        float sc = bn_g[col] * rsqrtf(bn_var[col] + 1e-5f);
        float sh = bn_b[col] - bn_mean[col] * sc;
        float bo = bias[col];
        float4 o;
        float* po = (float*)&o;
        #pragma unroll
        for (int i = 0; i < 4; i++) {
            float v = acc[i][j] + bo;
            v = v * sc + sh;
            po[i] = v / (1.f + expf(-v));   // SiLU
        }
        *reinterpret_cast<float4*>(&out[((size_t)n * C + col) * HW + hw0]) = o;
    }
}

// ============================================================
// launch
// ============================================================
extern "C" void kernel_launch(void* const* d_in, const int* in_sizes, int n_in,
                              void* d_out, int out_size)
{
    const float* x       = (const float*)d_in[0];
    const float* w_in    = (const float*)d_in[1];
    const float* b_in    = (const float*)d_in[2];
    const float* w_dw    = (const float*)d_in[3];
    const float* b_dw    = (const float*)d_in[4];
    const float* ln_g    = (const float*)d_in[5];
    const float* ln_b    = (const float*)d_in[6];
    const float* w_off   = (const float*)d_in[7];
    const float* b_off   = (const float*)d_in[8];
    const float* w_mask  = (const float*)d_in[9];
    const float* b_mask  = (const float*)d_in[10];
    const float* w_out   = (const float*)d_in[11];
    const float* b_out   = (const float*)d_in[12];
    const float* bn_g    = (const float*)d_in[13];
    const float* bn_b    = (const float*)d_in[14];
    const float* bn_mean = (const float*)d_in[15];
    const float* bn_var  = (const float*)d_in[16];
    float* out = (float*)d_out;

    transpose_kernel<<<dim3(HW / 32, C / 32, NB), dim3(32, 8)>>>(x);
    gemm_in_kernel  <<<dim3(C / 64, NPIX / 64), 256>>>(w_in, b_in);
    dwln_kernel     <<<NPIX, 256>>>(w_dw, b_dw, ln_g, ln_b);
    gemm_off_kernel <<<dim3((NOFF + 63) / 64, NPIX / 64), 256>>>(w_off, b_off);
    gemm_mask_kernel<<<dim3((NMSK + 63) / 64, NPIX / 64), 256>>>(w_mask, b_mask);
    sample_kernel   <<<NPIX, 256>>>();
    gemm_out_kernel <<<dim3(C / 64, NPIX / 64), 256>>>(w_out, b_out, bn_g, bn_b,
                                                       bn_mean, bn_var, out);
}

// round 2
// speedup vs baseline: 1.6188x; 1.6188x over previous
#include <cuda_runtime.h>
#include <math.h>

// Problem constants
#define NB   4
#define C    256
#define H    64
#define W    64
#define HW   4096
#define NPIX 16384          // NB*H*W
#define G    8
#define GC   32
#define P    9
#define NOFF 144            // G*P*2
#define NMSK 72             // G*P

// GEMM tiling
#define BM 128
#define BN 128
#define BK 32
#define PADT 136            // smem row pitch (floats): bank = 8k + m  -> conflict-free frags

// -------- scratch (device globals; no allocation allowed) --------
__device__ float g_xnhwc[NPIX * C];   // x transposed to NHWC
__device__ float g_xproj[NPIX * C];   // input projection (NHWC)
__device__ float g_x1   [NPIX * C];   // LN+GELU branch (NHWC)
__device__ float g_off  [NPIX * NOFF];
__device__ float g_mlog [NPIX * NMSK];
__device__ float g_agg  [NPIX * C];   // sampled+aggregated (NHWC)

__device__ __forceinline__ unsigned f2tf(float f) {
    unsigned r; asm("cvt.rna.tf32.f32 %0, %1;" : "=r"(r) : "f"(f)); return r;
}

// ============================================================
// NCHW -> NHWC transpose
// ============================================================
extern "C" __global__ void __launch_bounds__(256)
transpose_kernel(const float* __restrict__ x)
{
    __shared__ float tile[32][33];
    const int n   = blockIdx.z;
    const int hw0 = blockIdx.x * 32;
    const int c0  = blockIdx.y * 32;
    const float* src = x + (size_t)n * C * HW;
    float*       dst = g_xnhwc + (size_t)n * HW * C;
    #pragma unroll
    for (int i = 0; i < 4; i++) {
        int cl = threadIdx.y + i * 8;
        tile[cl][threadIdx.x] = src[(size_t)(c0 + cl) * HW + hw0 + threadIdx.x];
    }
    __syncthreads();
    #pragma unroll
    for (int i = 0; i < 4; i++) {
        int hl = threadIdx.y + i * 8;
        dst[(size_t)(hw0 + hl) * C + c0 + threadIdx.x] = tile[threadIdx.x][hl];
    }
}

// ============================================================
// tf32 mma.sync GEMM core.  A[M x 256] row-major fp32.
// MODE 0: dense B[256 x 256].  MODE 1: B = concat(w_off[256x144], w_mask[256x72]).
// acc[mf][nf][r] per-thread fragments of a 64x32 warp tile (warp grid 2x4).
// ============================================================
template<int MODE>
__device__ __forceinline__ void gemm_core(
    const float* __restrict__ A,
    const float* __restrict__ B0, const float* __restrict__ B1,
    int bm, int bn, float acc[4][4][4])
{
    __shared__ float As[BK][PADT];
    __shared__ float Bs[BK][PADT];
    const int tid  = threadIdx.x;
    const int warp = tid >> 5, lane = tid & 31;
    const int gid  = lane >> 2, tig = lane & 3;
    const int wm   = warp >> 2, wn = warp & 3;

    float4 aReg[4], bReg[4];

    auto loadAB = [&](int k0) {
        #pragma unroll
        for (int i = 0; i < 4; i++)
            aReg[i] = *reinterpret_cast<const float4*>(
                &A[(size_t)(bm + lane + 32 * i) * 256 + k0 + warp * 4]);
        #pragma unroll
        for (int i = 0; i < 4; i++) {
            int k = k0 + warp + 8 * i;
            if (MODE == 0) {
                bReg[i] = *reinterpret_cast<const float4*>(&B0[(size_t)k * 256 + bn + lane * 4]);
            } else {
                int c = bn + lane * 4;
                if (c < NOFF)
                    bReg[i] = *reinterpret_cast<const float4*>(&B0[(size_t)k * NOFF + c]);
                else if (c < NOFF + NMSK)
                    bReg[i] = *reinterpret_cast<const float4*>(&B1[(size_t)k * NMSK + c - NOFF]);
                else
                    bReg[i] = make_float4(0.f, 0.f, 0.f, 0.f);
            }
        }
    };

    auto stage = [&]() {
        #pragma unroll
        for (int i = 0; i < 4; i++) {
            int m = lane + 32 * i;
            As[warp * 4 + 0][m] = __uint_as_float(f2tf(aReg[i].x));
            As[warp * 4 + 1][m] = __uint_as_float(f2tf(aReg[i].y));
            As[warp * 4 + 2][m] = __uint_as_float(f2tf(aReg[i].z));
            As[warp * 4 + 3][m] = __uint_as_float(f2tf(aReg[i].w));
            float4 bt;
            bt.x = __uint_as_float(f2tf(bReg[i].x));
            bt.y = __uint_as_float(f2tf(bReg[i].y));
            bt.z = __uint_as_float(f2tf(bReg[i].z));
            bt.w = __uint_as_float(f2tf(bReg[i].w));
            *reinterpret_cast<float4*>(&Bs[warp + 8 * i][lane * 4]) = bt;
        }
    };

    loadAB(0);
    for (int k0 = 0; k0 < 256; k0 += BK) {
        __syncthreads();
        stage();
        __syncthreads();
        if (k0 + BK < 256) loadAB(k0 + BK);
        #pragma unroll
        for (int ks = 0; ks < 4; ks++) {
            unsigned a[4][4], b[4][2];
            #pragma unroll
            for (int mf = 0; mf < 4; mf++) {
                int m0 = wm * 64 + mf * 16;
                a[mf][0] = __float_as_uint(As[ks * 8 + tig    ][m0 + gid    ]);
                a[mf][1] = __float_as_uint(As[ks * 8 + tig    ][m0 + gid + 8]);
                a[mf][2] = __float_as_uint(As[ks * 8 + tig + 4][m0 + gid    ]);
                a[mf][3] = __float_as_uint(As[ks * 8 + tig + 4][m0 + gid + 8]);
            }
            #pragma unroll
            for (int nf = 0; nf < 4; nf++) {
                int n0 = wn * 32 + nf * 8;
                b[nf][0] = __float_as_uint(Bs[ks * 8 + tig    ][n0 + gid]);
                b[nf][1] = __float_as_uint(Bs[ks * 8 + tig + 4][n0 + gid]);
            }
            #pragma unroll
            for (int mf = 0; mf < 4; mf++)
                #pragma unroll
                for (int nf = 0; nf < 4; nf++)
                    asm volatile(
                        "mma.sync.aligned.m16n8k8.row.col.f32.tf32.tf32.f32 "
                        "{%0,%1,%2,%3},{%4,%5,%6,%7},{%8,%9},{%0,%1,%2,%3};"
                        : "+f"(acc[mf][nf][0]), "+f"(acc[mf][nf][1]),
                          "+f"(acc[mf][nf][2]), "+f"(acc[mf][nf][3])
                        : "r"(a[mf][0]), "r"(a[mf][1]), "r"(a[mf][2]), "r"(a[mf][3]),
                          "r"(b[nf][0]), "r"(b[nf][1]));
        }
    }
}

// ---- input projection: g_xnhwc @ w_in + b_in -> g_xproj ----
extern "C" __global__ void __launch_bounds__(256)
gemm_in_kernel(const float* __restrict__ Bw, const float* __restrict__ bias)
{
    float acc[4][4][4] = {};
    const int bm = blockIdx.y * BM, bn = blockIdx.x * BN;
    gemm_core<0>(g_xnhwc, Bw, nullptr, bm, bn, acc);
    const int lane = threadIdx.x & 31, warp = threadIdx.x >> 5;
    const int gid = lane >> 2, tig = lane & 3, wm = warp >> 2, wn = warp & 3;
    #pragma unroll
    for (int mf = 0; mf < 4; mf++) {
        int r0 = bm + wm * 64 + mf * 16 + gid;
        #pragma unroll
        for (int nf = 0; nf < 4; nf++) {
            int col = bn + wn * 32 + nf * 8 + 2 * tig;
            float bx = bias[col], by = bias[col + 1];
            float2 lo = {acc[mf][nf][0] + bx, acc[mf][nf][1] + by};
            float2 hi = {acc[mf][nf][2] + bx, acc[mf][nf][3] + by};
            *reinterpret_cast<float2*>(&g_xproj[(size_t)r0 * 256 + col])       = lo;
            *reinterpret_cast<float2*>(&g_xproj[(size_t)(r0 + 8) * 256 + col]) = hi;
        }
    }
}

// ---- fused offset+mask projection: g_x1 @ [w_off|w_mask] ----
extern "C" __global__ void __launch_bounds__(256)
gemm_offmask_kernel(const float* __restrict__ Bo, const float* __restrict__ Bm,
                    const float* __restrict__ bo, const float* __restrict__ bmk)
{
    float acc[4][4][4] = {};
    const int bm = blockIdx.y * BM, bn = blockIdx.x * BN;
    gemm_core<1>(g_x1, Bo, Bm, bm, bn, acc);
    const int lane = threadIdx.x & 31, warp = threadIdx.x >> 5;
    const int gid = lane >> 2, tig = lane & 3, wm = warp >> 2, wn = warp & 3;
    #pragma unroll
    for (int mf = 0; mf < 4; mf++) {
        int r0 = bm + wm * 64 + mf * 16 + gid;
        #pragma unroll
        for (int nf = 0; nf < 4; nf++) {
            int col = bn + wn * 32 + nf * 8 + 2 * tig;
            if (col >= NOFF + NMSK) continue;
            float bx, by;
            float* d0; float* d1; int str;
            if (col < NOFF) {
                bx = bo[col]; by = bo[col + 1];
                d0 = &g_off[(size_t)r0 * NOFF + col];
                d1 = &g_off[(size_t)(r0 + 8) * NOFF + col];
            } else {
                int mc = col - NOFF;
                bx = bmk[mc]; by = bmk[mc + 1];
                d0 = &g_mlog[(size_t)r0 * NMSK + mc];
                d1 = &g_mlog[(size_t)(r0 + 8) * NMSK + mc];
            }
            (void)str;
            float2 lo = {acc[mf][nf][0] + bx, acc[mf][nf][1] + by};
            float2 hi = {acc[mf][nf][2] + bx, acc[mf][nf][3] + by};
            *reinterpret_cast<float2*>(d0) = lo;
            *reinterpret_cast<float2*>(d1) = hi;
        }
    }
}

// ---- output projection + bias + BN + SiLU -> NCHW ----
extern "C" __global__ void __launch_bounds__(256)
gemm_out_kernel(const float* __restrict__ Bw, const float* __restrict__ bias,
                const float* __restrict__ bn_g, const float* __restrict__ bn_b,
                const float* __restrict__ bn_mean, const float* __restrict__ bn_var,
                float* __restrict__ out)
{
    float acc[4][4][4] = {};
    const int bm = blockIdx.y * BM, bn = blockIdx.x * BN;
    gemm_core<0>(g_agg, Bw, nullptr, bm, bn, acc);
    const int lane = threadIdx.x & 31, warp = threadIdx.x >> 5;
    const int gid = lane >> 2, tig = lane & 3, wm = warp >> 2, wn = warp & 3;
    #pragma unroll
    for (int nf = 0; nf < 4; nf++) {
        int colb = bn + wn * 32 + nf * 8 + 2 * tig;
        #pragma unroll
        for (int j = 0; j < 2; j++) {
            int col = colb + j;
            float sc = bn_g[col] * rsqrtf(bn_var[col] + 1e-5f);
            float sh = bn_b[col] - bn_mean[col] * sc;
            float bo = bias[col];
            #pragma unroll
            for (int mf = 0; mf < 4; mf++) {
                #pragma unroll
                for (int h2 = 0; h2 < 2; h2++) {
                    int row = bm + wm * 64 + mf * 16 + gid + 8 * h2;
                    float v = acc[mf][nf][2 * h2 + j] + bo;
                    v = v * sc + sh;
                    v = v / (1.f + expf(-v));
                    int n = row >> 12, hw = row & 4095;
                    out[((size_t)n * C + col) * HW + hw] = v;
                }
            }
        }
    }
}

// ============================================================
// Depthwise 3x3 (pad 1) + LayerNorm(C) + exact GELU, fused.
// ============================================================
extern "C" __global__ void __launch_bounds__(256)
dwln_kernel(const float* __restrict__ w_dw, const float* __restrict__ b_dw,
            const float* __restrict__ ln_g, const float* __restrict__ ln_b)
{
    const int pix = blockIdx.x;
    const int c   = threadIdx.x;
    const int n = pix >> 12, hw = pix & 4095, h = hw >> 6, w = hw & 63;

    float wk[9];
    #pragma unroll
    for (int i = 0; i < 9; i++) wk[i] = w_dw[c * 9 + i];

    float acc = b_dw[c];
    #pragma unroll
    for (int ky = 0; ky < 3; ky++) {
        int yy = h + ky - 1;
        if (yy < 0 || yy > 63) continue;
        #pragma unroll
        for (int kx = 0; kx < 3; kx++) {
            int xx = w + kx - 1;
            if (xx < 0 || xx > 63) continue;
            acc += g_xnhwc[(((size_t)n * 64 + yy) * 64 + xx) * C + c] * wk[ky * 3 + kx];
        }
    }

    __shared__ float red[8];
    float s = acc;
    #pragma unroll
    for (int o = 16; o; o >>= 1) s += __shfl_xor_sync(0xffffffffu, s, o);
    if ((c & 31) == 0) red[c >> 5] = s;
    __syncthreads();
    float tot = 0.f;
    #pragma unroll
    for (int i = 0; i < 8; i++) tot += red[i];
    const float mean = tot * (1.f / 256.f);
    __syncthreads();
    float d  = acc - mean;
    float s2 = d * d;
    #pragma unroll
    for (int o = 16; o; o >>= 1) s2 += __shfl_xor_sync(0xffffffffu, s2, o);
    if ((c & 31) == 0) red[c >> 5] = s2;
    __syncthreads();
    float tot2 = 0.f;
    #pragma unroll
    for (int i = 0; i < 8; i++) tot2 += red[i];
    const float var = tot2 * (1.f / 256.f);

    float v = d * rsqrtf(var + 1e-5f) * ln_g[c] + ln_b[c];
    float ge = 0.5f * v * (1.f + erff(v * 0.70710678118654752f));
    g_x1[(size_t)pix * C + c] = ge;
}

// ============================================================
// Deformable sampling + per-group softmax mask aggregation.
// ============================================================
extern "C" __global__ void __launch_bounds__(256)
sample_kernel()
{
    const int pix = blockIdx.x;
    const int t   = threadIdx.x;
    const int g   = t >> 5, cc = t & 31;
    const int n = pix >> 12, hw = pix & 4095, h = hw >> 6, w = hw & 63;

    const float* ob = g_off  + (size_t)pix * NOFF + g * 18;
    const float* lb = g_mlog + (size_t)pix * NMSK + g * 9;

    float l[9], m = -1e30f;
    #pragma unroll
    for (int p = 0; p < 9; p++) { l[p] = lb[p]; m = fmaxf(m, l[p]); }
    float se = 0.f;
    #pragma unroll
    for (int p = 0; p < 9; p++) { l[p] = expf(l[p] - m); se += l[p]; }
    const float inv = 1.f / se;

    const float* base = g_xproj + (size_t)n * HW * C + g * GC + cc;
    float acc = 0.f;
    #pragma unroll
    for (int p = 0; p < 9; p++) {
        float gx = (float)(w + (p / 3)) + ob[2 * p + 0];
        float gy = (float)(h + (p % 3)) + ob[2 * p + 1];
        float x0f = floorf(gx), y0f = floorf(gy);
        int   x0 = (int)x0f, y0 = (int)y0f;
        float wx = gx - x0f, wy = gy - y0f;
        float w00 = (1.f - wx) * (1.f - wy);
        float w10 = wx * (1.f - wy);
        float w01 = (1.f - wx) * wy;
        float w11 = wx * wy;
        bool yi0 = (y0     >= 1 && y0     <= 64);
        bool yi1 = (y0 + 1 >= 1 && y0 + 1 <= 64);
        bool xi0 = (x0     >= 1 && x0     <= 64);
        bool xi1 = (x0 + 1 >= 1 && x0 + 1 <= 64);
        float v00 = 0.f, v10 = 0.f, v01 = 0.f, v11 = 0.f;
        if (yi0 && xi0) v00 = base[((size_t)(y0 - 1) * 64 + (x0 - 1)) * C];
        if (yi0 && xi1) v10 = base[((size_t)(y0 - 1) * 64 + (x0    )) * C];
        if (yi1 && xi0) v01 = base[((size_t)(y0    ) * 64 + (x0 - 1)) * C];
        if (yi1 && xi1) v11 = base[((size_t)(y0    ) * 64 + (x0    )) * C];
        acc += (l[p] * inv) * (w00 * v00 + w10 * v10 + w01 * v01 + w11 * v11);
    }
    g_agg[(size_t)pix * C + t] = acc;
}

// ============================================================
// launch
// ============================================================
extern "C" void kernel_launch(void* const* d_in, const int* in_sizes, int n_in,
                              void* d_out, int out_size)
{
    const float* x       = (const float*)d_in[0];
    const float* w_in    = (const float*)d_in[1];
    const float* b_in    = (const float*)d_in[2];
    const float* w_dw    = (const float*)d_in[3];
    const float* b_dw    = (const float*)d_in[4];
    const float* ln_g    = (const float*)d_in[5];
    const float* ln_b    = (const float*)d_in[6];
    const float* w_off   = (const float*)d_in[7];
    const float* b_off   = (const float*)d_in[8];
    const float* w_mask  = (const float*)d_in[9];
    const float* b_mask  = (const float*)d_in[10];
    const float* w_out   = (const float*)d_in[11];
    const float* b_out   = (const float*)d_in[12];
    const float* bn_g    = (const float*)d_in[13];
    const float* bn_b    = (const float*)d_in[14];
    const float* bn_mean = (const float*)d_in[15];
    const float* bn_var  = (const float*)d_in[16];
    float* out = (float*)d_out;

    transpose_kernel   <<<dim3(HW / 32, C / 32, NB), dim3(32, 8)>>>(x);
    gemm_in_kernel     <<<dim3(C / BN, NPIX / BM), 256>>>(w_in, b_in);
    dwln_kernel        <<<NPIX, 256>>>(w_dw, b_dw, ln_g, ln_b);
    gemm_offmask_kernel<<<dim3(2, NPIX / BM), 256>>>(w_off, w_mask, b_off, b_mask);
    sample_kernel      <<<NPIX, 256>>>();
    gemm_out_kernel    <<<dim3(C / BN, NPIX / BM), 256>>>(w_out, b_out, bn_g, bn_b,
                                                          bn_mean, bn_var, out);
}